// round 15
// baseline (speedup 1.0000x reference)
#include <cuda_runtime.h>
#include <cuda_bf16.h>
#include <cstdint>
#include <cstddef>

#define BATCH 64
#define SEQ   512
#define DIM   512
#define HID   256
#define NK    32

typedef unsigned long long u64;

// ---------------- scratch (__device__ globals; no allocation) ----------------
// xp layout: [t*64+b][g]  ((t*64+b)*2048 + g)
__device__ float g_xp[(size_t)SEQ * BATCH * 2048];          // 256 MiB
__device__ float g_hout[(size_t)2 * SEQ * HID * BATCH];     // 64 MiB:  [dir][t][j][b]
__device__ __nv_bfloat16 g_hhi[2 * 2 * BATCH * HID];        // [dir][buf][b][k] bf16 hi
__device__ __nv_bfloat16 g_hlo[2 * 2 * BATCH * HID];        // [dir][buf][b][k] bf16 lo
__device__ __nv_bfloat16 g_xhi[(size_t)32768 * 512];
__device__ __nv_bfloat16 g_xlo[(size_t)32768 * 512];
__device__ __nv_bfloat16 g_whi[(size_t)2048 * 512];
__device__ __nv_bfloat16 g_wlo[(size_t)2048 * 512];
__device__ unsigned g_gcnt[8 * 32];                         // 8 group counters, 128B apart
__device__ unsigned g_xcnt[4 * 32];                         // 4 tchunk counters, 128B apart

// ---------------- mma.sync / ldmatrix / cp.async helpers ----------------
__device__ __forceinline__ uint32_t smem_to_u32(const void* p) {
    uint32_t a;
    asm("{ .reg .u64 t; cvta.to.shared.u64 t, %1; cvt.u32.u64 %0, t; }" : "=r"(a) : "l"(p));
    return a;
}
__device__ __forceinline__ void cp_async16(uint32_t saddr, const void* gptr) {
    asm volatile("cp.async.cg.shared.global [%0], [%1], 16;" :: "r"(saddr), "l"(gptr));
}
#define CP_COMMIT() asm volatile("cp.async.commit_group;")
#define CP_WAIT(n)  asm volatile("cp.async.wait_group %0;" :: "n"(n) : "memory")

__device__ __forceinline__ void ldsm4(uint32_t* r, uint32_t addr) {
    asm volatile("ldmatrix.sync.aligned.m8n8.x4.shared.b16 {%0,%1,%2,%3}, [%4];"
        : "=r"(r[0]), "=r"(r[1]), "=r"(r[2]), "=r"(r[3]) : "r"(addr));
}
__device__ __forceinline__ void ldsm2(uint32_t* r, uint32_t addr) {
    asm volatile("ldmatrix.sync.aligned.m8n8.x2.shared.b16 {%0,%1}, [%2];"
        : "=r"(r[0]), "=r"(r[1]) : "r"(addr));
}
__device__ __forceinline__ void mma16816(float* c, const uint32_t* a, uint32_t b0, uint32_t b1) {
    asm volatile("mma.sync.aligned.m16n8k16.row.col.f32.bf16.bf16.f32 "
        "{%0,%1,%2,%3}, {%4,%5,%6,%7}, {%8,%9}, {%0,%1,%2,%3};"
        : "+f"(c[0]), "+f"(c[1]), "+f"(c[2]), "+f"(c[3])
        : "r"(a[0]), "r"(a[1]), "r"(a[2]), "r"(a[3]), "r"(b0), "r"(b1));
}

// ---------------- group barrier (16 CTAs, monotonic, split arrive/wait) -----
__device__ __forceinline__ void barrier_arrive(unsigned* cnt)
{
    __syncthreads();
    if (threadIdx.x == 0)
        asm volatile("red.release.gpu.add.u32 [%0], 1;" :: "l"(cnt) : "memory");
}
__device__ __forceinline__ void barrier_wait(unsigned* cnt, unsigned target)
{
    if (threadIdx.x == 0) {
        unsigned v;
        while (true) {
            asm volatile("ld.acquire.gpu.u32 %0, [%1];" : "=r"(v) : "l"(cnt) : "memory");
            if (v >= target) break;
            __nanosleep(20);
        }
    }
    __syncthreads();
}

__global__ void reset_counters_kernel()
{
    if (threadIdx.x < 8 * 32) g_gcnt[threadIdx.x] = 0;
    if (threadIdx.x < 4 * 32) g_xcnt[threadIdx.x] = 0;
}

// ---------------- Kernel 0: fp32 -> bf16 hi/lo split (vectorized) -----------
__global__ __launch_bounds__(256) void split_kernel(
    const float4* __restrict__ src, uint2* __restrict__ hi,
    uint2* __restrict__ lo, int n4)
{
    int stride = gridDim.x * blockDim.x;
    for (int i = blockIdx.x * blockDim.x + threadIdx.x; i < n4; i += stride) {
        float4 v = src[i];
        __nv_bfloat16 hx = __float2bfloat16(v.x);
        __nv_bfloat16 hy = __float2bfloat16(v.y);
        __nv_bfloat16 hz = __float2bfloat16(v.z);
        __nv_bfloat16 hw = __float2bfloat16(v.w);
        __nv_bfloat16 lx = __float2bfloat16(v.x - __bfloat162float(hx));
        __nv_bfloat16 ly = __float2bfloat16(v.y - __bfloat162float(hy));
        __nv_bfloat16 lz = __float2bfloat16(v.z - __bfloat162float(hz));
        __nv_bfloat16 lw = __float2bfloat16(v.w - __bfloat162float(hw));
        uint2 H, L;
        H.x = (uint32_t)__bfloat16_as_ushort(hx) | ((uint32_t)__bfloat16_as_ushort(hy) << 16);
        H.y = (uint32_t)__bfloat16_as_ushort(hz) | ((uint32_t)__bfloat16_as_ushort(hw) << 16);
        L.x = (uint32_t)__bfloat16_as_ushort(lx) | ((uint32_t)__bfloat16_as_ushort(ly) << 16);
        L.y = (uint32_t)__bfloat16_as_ushort(lz) | ((uint32_t)__bfloat16_as_ushort(lw) << 16);
        hi[i] = H; lo[i] = L;
    }
}

// ---------------- gemm part (device) -----------------------------------------
#define NCHUNK 32
__device__ __forceinline__ void gemm_part(char* dsm, int by,
    const float* __restrict__ bf_, const float* __restrict__ bb_)
{
    __shared__ float s_bias[128];

    const int tid  = threadIdx.x;
    const int lane = tid & 31;
    const int wid  = tid >> 5;
    const int wm   = wid >> 2;
    const int wn   = wid & 3;
    const int nTile = by & 15;
    const int myt   = by >> 4;
    const int grp   = myt >> 6;
    const int tsel  = (0x2130 >> (grp * 4)) & 0xF;   // order: 0,3,1,2
    const int mTile = (myt & 63) * 4 + tsel;
    const int mBase = mTile * 128;
    const int nBase = nTile * 128;

    if (tid < 128) {
        const float* bsrc = (nTile < 8) ? bf_ : bb_;
        int boff = (nTile < 8) ? nTile * 128 : (nTile - 8) * 128;
        s_bias[tid] = bsrc[boff + tid];
    }

    const uint32_t smem_base = smem_to_u32(dsm);

    uint32_t aoff[2][4];
    {
        const int arow = wm * 64 + (lane & 15);
        const int akc  = lane >> 4;
#pragma unroll
        for (int mf = 0; mf < 4; mf++) {
            const int r = arow + mf * 16;
            const uint32_t o = (uint32_t)(r * 32 + ((akc ^ ((r >> 2) & 1)) << 4));
            aoff[0][mf] = o;
            aoff[1][mf] = o + 4096u;
        }
    }
    uint32_t boff[2][2];
    {
        const int nrow = wn * 32 + (lane & 7) + ((lane >> 4) << 3);
        const int bkc  = (lane >> 3) & 1;
#pragma unroll
        for (int p = 0; p < 2; p++) {
            const int r = nrow + p * 16;
            const uint32_t o = (uint32_t)(r * 32 + ((bkc ^ ((r >> 2) & 1)) << 4));
            boff[0][p] = o + 8192u;
            boff[1][p] = o + 12288u;
        }
    }

    const int ldrow = tid >> 1;
    const int ldck  = tid & 1;
    const uint32_t ld_soff = (uint32_t)(ldrow * 32 + ((ldck ^ ((ldrow >> 2) & 1)) << 4));
    const __nv_bfloat16* Ahg = g_xhi + (size_t)(mBase + ldrow) * 512 + ldck * 8;
    const __nv_bfloat16* Alg = g_xlo + (size_t)(mBase + ldrow) * 512 + ldck * 8;
    const __nv_bfloat16* Bhg = g_whi + (size_t)(nBase + ldrow) * 512 + ldck * 8;
    const __nv_bfloat16* Blg = g_wlo + (size_t)(nBase + ldrow) * 512 + ldck * 8;

    float cr[4][4][4];
#pragma unroll
    for (int mf = 0; mf < 4; mf++)
#pragma unroll
        for (int nf = 0; nf < 4; nf++)
#pragma unroll
            for (int q = 0; q < 4; q++) cr[mf][nf][q] = 0.f;

#pragma unroll
    for (int s = 0; s < 2; s++) {
        const int kb = s * 16;
        const uint32_t so = smem_base + s * 16384u + ld_soff;
        cp_async16(so,          Ahg + kb);
        cp_async16(so + 4096u,  Alg + kb);
        cp_async16(so + 8192u,  Bhg + kb);
        cp_async16(so + 12288u, Blg + kb);
        CP_COMMIT();
    }

    int cb = 0;
    int ib = 2;
    for (int c = 0; c < NCHUNK; c++) {
        if (c + 1 < NCHUNK) { CP_WAIT(1); } else { CP_WAIT(0); }
        __syncthreads();

        if (c + 2 < NCHUNK) {
            const int kb = (c + 2) * 16;
            const uint32_t so = smem_base + ib * 16384u + ld_soff;
            cp_async16(so,          Ahg + kb);
            cp_async16(so + 4096u,  Alg + kb);
            cp_async16(so + 8192u,  Bhg + kb);
            cp_async16(so + 12288u, Blg + kb);
            CP_COMMIT();
        }

        const uint32_t stg = smem_base + cb * 16384u;

        uint32_t ah[4][4];
#pragma unroll
        for (int mf = 0; mf < 4; mf++) ldsm4(ah[mf], stg + aoff[0][mf]);
        uint32_t bh[2][4];
#pragma unroll
        for (int p = 0; p < 2; p++) ldsm4(bh[p], stg + boff[0][p]);
#pragma unroll
        for (int mf = 0; mf < 4; mf++)
#pragma unroll
            for (int nf = 0; nf < 4; nf++)
                mma16816(cr[mf][nf], ah[mf], bh[nf >> 1][2 * (nf & 1)], bh[nf >> 1][2 * (nf & 1) + 1]);

        uint32_t bl[2][4];
#pragma unroll
        for (int p = 0; p < 2; p++) ldsm4(bl[p], stg + boff[1][p]);
#pragma unroll
        for (int mf = 0; mf < 4; mf++)
#pragma unroll
            for (int nf = 0; nf < 4; nf++)
                mma16816(cr[mf][nf], ah[mf], bl[nf >> 1][2 * (nf & 1)], bl[nf >> 1][2 * (nf & 1) + 1]);

        uint32_t al[4][4];
#pragma unroll
        for (int mf = 0; mf < 4; mf++) ldsm4(al[mf], stg + aoff[1][mf]);
#pragma unroll
        for (int mf = 0; mf < 4; mf++)
#pragma unroll
            for (int nf = 0; nf < 4; nf++)
                mma16816(cr[mf][nf], al[mf], bh[nf >> 1][2 * (nf & 1)], bh[nf >> 1][2 * (nf & 1) + 1]);

        cb = (cb == 2) ? 0 : cb + 1;
        ib = (ib == 2) ? 0 : ib + 1;
    }

#pragma unroll
    for (int mf = 0; mf < 4; mf++) {
        const int m0 = mBase + wm * 64 + mf * 16 + (lane >> 2);
        const int m1 = m0 + 8;
        const size_t r0 = ((size_t)(m0 & 511) * 64 + (m0 >> 9)) * 2048;
        const size_t r1 = ((size_t)(m1 & 511) * 64 + (m1 >> 9)) * 2048;
#pragma unroll
        for (int nf = 0; nf < 4; nf++) {
            const int nl = wn * 32 + nf * 8 + (lane & 3) * 2;
            const float b0 = s_bias[nl], b1 = s_bias[nl + 1];
            const int n = nBase + nl;
            float2 v0 = make_float2(cr[mf][nf][0] + b0, cr[mf][nf][1] + b1);
            float2 v1 = make_float2(cr[mf][nf][2] + b0, cr[mf][nf][3] + b1);
            *(float2*)&g_xp[r0 + n] = v0;
            *(float2*)&g_xp[r1 + n] = v1;
        }
    }

    // publish tchunk completion (release; syncthreads covers all threads' stores)
    __syncthreads();
    if (tid == 0)
        asm volatile("red.release.gpu.add.u32 [%0], 1;" :: "l"(&g_xcnt[tsel * 32]) : "memory");
}

// ---------------- lstm part (device) -----------------------------------------
__device__ __forceinline__ void lstm_part(char* dynb, int cta,
    const float* __restrict__ Whh_f, const float* __restrict__ Whh_b,
    const int* __restrict__ lengths)
{
    char*  smWh = dynb;                       // 32768
    char*  smWl = dynb + 32768;               // 32768
    char*  smHh = dynb + 65536;               // 8192
    char*  smHl = dynb + 73728;               // 8192
    float* gsm  = (float*)(dynb + 81920);     // 64*18 floats
    float* xsm  = (float*)(dynb + 86528);     // 2*1088 floats

    const int tid = threadIdx.x;
    const int dir = cta >> 6;
    const int s   = (cta >> 2) & 15;
    const int gb  = cta & 3;
    const int s16   = s * 16;
    const int bbase = gb * 16;
    const float* Whh = dir ? Whh_b : Whh_f;
    unsigned* gcnt = &g_gcnt[(dir * 4 + gb) * 32];

    for (int idx = tid; idx < 64 * 256; idx += 256) {
        int r = idx >> 8, k = idx & 255;
        int q = r >> 4, jj = r & 15;
        float wv = Whh[(q * 256 + s16 + jj) * 256 + k];
        __nv_bfloat16 hi = __float2bfloat16(wv);
        __nv_bfloat16 lo = __float2bfloat16(wv - __bfloat162float(hi));
        int kc = k >> 3, ko = k & 7;
        int off = r * 512 + ((kc ^ (r & 7)) << 4) + ko * 2;
        *(__nv_bfloat16*)(smWh + off) = hi;
        *(__nv_bfloat16*)(smWl + off) = lo;
    }

    const int j = tid >> 4;
    const int b = tid & 15;
    const int len_b = lengths[bbase + b];

    {
        size_t o = ((size_t)(dir * 2 + 0) * 64 + bbase + b) * 256 + s16 + j;
        g_hhi[o] = __float2bfloat16(0.f);
        g_hlo[o] = __float2bfloat16(0.f);
    }

    const uint32_t xsm_addr = smem_to_u32(xsm);
    const uint32_t hh_addr  = smem_to_u32(smHh);
    const uint32_t hl_addr  = smem_to_u32(smHl);
    const uint32_t wh_addr  = smem_to_u32(smWh);
    const uint32_t wl_addr  = smem_to_u32(smWl);

    unsigned tc_mask = 0;
#define WAIT_XP(tc_) do { int _tc = (tc_); \
    if (!(tc_mask & (1u << _tc))) { \
        if (threadIdx.x == 0) { unsigned v; \
            while (true) { \
                asm volatile("ld.acquire.gpu.u32 %0, [%1];" : "=r"(v) : "l"(&g_xcnt[_tc * 32]) : "memory"); \
                if (v >= 1024u) break; __nanosleep(40); } } \
        __syncthreads(); \
        tc_mask |= (1u << _tc); } } while (0)

    // prologue xp prefetch (step 0 -> buf 0)
    {
        const int t0 = dir ? (SEQ - 1) : 0;
        WAIT_XP(t0 >> 7);
        const int r = tid >> 2, c = tid & 3;
        const int pb = r >> 2, pq = r & 3;
        cp_async16(xsm_addr + (uint32_t)((pb * 68 + pq * 16 + c * 4) * 4),
                   &g_xp[((size_t)t0 * 64 + bbase + pb) * 2048 + dir * 1024 + pq * 256 + s16 + c * 4]);
        CP_COMMIT();
    }
    barrier_arrive(gcnt);
    barrier_wait(gcnt, 16u);

    const int lane = tid & 31;
    const int wrp  = tid >> 5;
    const int mf   = wrp >> 1;
    const int nb8  = wrp & 1;
    const int rowA = mf * 16 + (lane & 15);
    const int halfA = lane >> 4;
    const int rowB = nb8 * 8 + (lane & 7);
    const int halfB = (lane >> 3) & 1;

    float c_st = 0.f, h_st = 0.f;

    for (int st = 0; st < SEQ; st++) {
        const int tstep = dir ? (SEQ - 1 - st) : st;
        const int cur   = st & 1;
        const int gbuf  = st & 1;

        {
            const __nv_bfloat16* shi = g_hhi + (size_t)(dir * 2 + gbuf) * 64 * 256;
            const __nv_bfloat16* slo = g_hlo + (size_t)(dir * 2 + gbuf) * 64 * 256;
#pragma unroll
            for (int r2 = 0; r2 < 2; r2++) {
                int cch = tid + r2 * 256;
                int n = cch >> 5, kc = cch & 31;
                uint32_t so = (uint32_t)(n * 512 + ((kc ^ (n & 7)) << 4));
                cp_async16(hh_addr + so, shi + (size_t)(bbase + n) * 256 + kc * 8);
                cp_async16(hl_addr + so, slo + (size_t)(bbase + n) * 256 + kc * 8);
            }
            CP_COMMIT();
        }
        CP_WAIT(0);
        __syncthreads();

        if (st + 1 < SEQ) {
            const int tn = dir ? (SEQ - 2 - st) : (st + 1);
            WAIT_XP(tn >> 7);
            const int r = tid >> 2, c = tid & 3;
            const int pb = r >> 2, pq = r & 3;
            cp_async16(xsm_addr + (uint32_t)(((cur ^ 1) * 1088 + pb * 68 + pq * 16 + c * 4) * 4),
                       &g_xp[((size_t)tn * 64 + bbase + pb) * 2048 + dir * 1024 + pq * 256 + s16 + c * 4]);
            CP_COMMIT();
        }

        float chh0[4] = {0,0,0,0}, chh1[4] = {0,0,0,0};
        float chl0[4] = {0,0,0,0}, chl1[4] = {0,0,0,0};
        float clh0[4] = {0,0,0,0}, clh1[4] = {0,0,0,0};
#pragma unroll
        for (int ks = 0; ks < 16; ks++) {
            const int kcA = ks * 2 + halfA;
            const uint32_t offA = (uint32_t)(rowA * 512 + ((kcA ^ (rowA & 7)) << 4));
            const int kcB = ks * 2 + halfB;
            const uint32_t offB = (uint32_t)(rowB * 512 + ((kcB ^ (rowB & 7)) << 4));
            uint32_t ah[4], al[4], bhp[2], blp[2];
            ldsm4(ah, wh_addr + offA);
            ldsm4(al, wl_addr + offA);
            ldsm2(bhp, hh_addr + offB);
            ldsm2(blp, hl_addr + offB);
            if (ks & 1) {
                mma16816(chh1, ah, bhp[0], bhp[1]);
                mma16816(chl1, ah, blp[0], blp[1]);
                mma16816(clh1, al, bhp[0], bhp[1]);
            } else {
                mma16816(chh0, ah, bhp[0], bhp[1]);
                mma16816(chl0, ah, blp[0], blp[1]);
                mma16816(clh0, al, bhp[0], bhp[1]);
            }
        }
        {
            const int r0  = mf * 16 + (lane >> 2);
            const int col = nb8 * 8 + 2 * (lane & 3);
            float2 v0 = make_float2(chh0[0] + chh1[0] + chl0[0] + chl1[0] + clh0[0] + clh1[0],
                                    chh0[1] + chh1[1] + chl0[1] + chl1[1] + clh0[1] + clh1[1]);
            float2 v1 = make_float2(chh0[2] + chh1[2] + chl0[2] + chl1[2] + clh0[2] + clh1[2],
                                    chh0[3] + chh1[3] + chl0[3] + chl1[3] + clh0[3] + clh1[3]);
            *(float2*)&gsm[r0 * 18 + col]       = v0;
            *(float2*)&gsm[(r0 + 8) * 18 + col] = v1;
        }
        __syncthreads();

        {
            const float* xq = xsm + cur * 1088 + b * 68;
            float a0 = gsm[(0 * 16 + j) * 18 + b] + xq[0 * 16 + j];
            float a1 = gsm[(1 * 16 + j) * 18 + b] + xq[1 * 16 + j];
            float a2 = gsm[(2 * 16 + j) * 18 + b] + xq[2 * 16 + j];
            float a3 = gsm[(3 * 16 + j) * 18 + b] + xq[3 * 16 + j];
            float i_ = __fdividef(1.f, 1.f + __expf(-a0));
            float f_ = __fdividef(1.f, 1.f + __expf(-a1));
            float g_ = tanhf(a2);
            float o_ = __fdividef(1.f, 1.f + __expf(-a3));
            float c_new = f_ * c_st + i_ * g_;
            float h_new = o_ * tanhf(c_new);
            bool  m = (tstep < len_b);
            c_st = m ? c_new : c_st;
            h_st = m ? h_new : h_st;
            __nv_bfloat16 hh = __float2bfloat16(h_st);
            __nv_bfloat16 hl = __float2bfloat16(h_st - __bfloat162float(hh));
            size_t o = ((size_t)(dir * 2 + (gbuf ^ 1)) * 64 + bbase + b) * 256 + s16 + j;
            g_hhi[o] = hh;
            g_hlo[o] = hl;
        }
        barrier_arrive(gcnt);
        g_hout[((size_t)(dir * SEQ + tstep) * HID + (s16 + j)) * 64 + bbase + b] = h_st;
        barrier_wait(gcnt, 16u * (st + 2));
    }
#undef WAIT_XP
}

// ---------------- fused kernel: LSTM CTAs 0..127, GEMM CTAs 128..4223 -------
__global__ void __launch_bounds__(256, 2) fused_kernel(
    const float* __restrict__ bf_, const float* __restrict__ bb_,
    const float* __restrict__ Whh_f, const float* __restrict__ Whh_b,
    const int* __restrict__ lengths)
{
    extern __shared__ __align__(128) char dynb[];
    if (blockIdx.x >= 128) {
        gemm_part(dynb, (int)blockIdx.x - 128, bf_, bb_);
    } else {
        lstm_part(dynb, (int)blockIdx.x, Whh_f, Whh_b, lengths);
    }
}

// ---------------- Kernel 3: logits = [h_f;h_b] @ W_clf^T + b_clf ----------------
__global__ __launch_bounds__(256) void clf_kernel(
    const float* __restrict__ Wclf, const float* __restrict__ bclf,
    float* __restrict__ out)
{
    __shared__ float Ws[32 * 65];
    __shared__ __align__(16) float hs[64 * 64];
    const int t   = blockIdx.x;
    const int tid = threadIdx.x;
    const int n   = tid & 31;
    const int bg  = tid >> 5;

    float acc[8];
#pragma unroll
    for (int i = 0; i < 8; i++) acc[i] = 0.f;

    for (int ch = 0; ch < 8; ch++) {
        const int dir = ch >> 2;
        const int jbase = (ch & 3) * 64;
        for (int l = tid; l < 2048; l += 256) {
            int nn = l >> 6, jj = l & 63;
            Ws[nn * 65 + jj] = Wclf[nn * 512 + dir * 256 + jbase + jj];
        }
        const float* hsrc = g_hout + ((size_t)(dir * SEQ + t) * HID + jbase) * 64;
#pragma unroll
        for (int r = 0; r < 4; r++)
            ((float4*)hs)[tid + r * 256] = __ldg(((const float4*)hsrc) + tid + r * 256);
        __syncthreads();
#pragma unroll 16
        for (int jj = 0; jj < 64; jj++) {
            float wv = Ws[n * 65 + jj];
            float4 hA = *(const float4*)&hs[jj * 64 + bg * 8];
            float4 hB = *(const float4*)&hs[jj * 64 + bg * 8 + 4];
            acc[0] += wv * hA.x; acc[1] += wv * hA.y; acc[2] += wv * hA.z; acc[3] += wv * hA.w;
            acc[4] += wv * hB.x; acc[5] += wv * hB.y; acc[6] += wv * hB.z; acc[7] += wv * hB.w;
        }
        __syncthreads();
    }
    const float bias = bclf[n];
#pragma unroll
    for (int bb = 0; bb < 8; bb++) {
        int b = bg * 8 + bb;
        out[((size_t)b * SEQ + t) * NK + n] = acc[bb] + bias;
    }
}

// ---------------- Kernel 4: Viterbi decode (smem-based) ----------------
__global__ __launch_bounds__(32) void viterbi_kernel(
    const float* __restrict__ logits, const int* __restrict__ lengths,
    const float* __restrict__ startt, const float* __restrict__ endt,
    const float* __restrict__ trans, float* __restrict__ preds, int write_preds)
{
    __shared__ float transT[32 * 33];
    __shared__ float sscore[2][32];
    __shared__ unsigned char hist[511][32];
    const int b = blockIdx.x;
    const int j = threadIdx.x;
    const int len = lengths[b];

#pragma unroll 4
    for (int i = 0; i < 32; i++) transT[j * 33 + i] = trans[i * 32 + j];

    const float* lg = logits + (size_t)b * SEQ * NK;
    float score = startt[j] + lg[j];
    float e_next = lg[NK + j];

    for (int t = 1; t < SEQ; t++) {
        const int buf = t & 1;
        sscore[buf][j] = score;
        __syncwarp();
        float e = e_next;
        if (t + 1 < SEQ) e_next = lg[(t + 1) * NK + j];

        float m0, m1; int a0, a1;
        float bestv = -3.4e38f; int besta = 0;
#pragma unroll
        for (int p = 0; p < 8; p++) {
            float4 s4 = *(const float4*)&sscore[buf][p * 4];
            float v0 = s4.x + transT[j * 33 + p * 4 + 0];
            float v1 = s4.y + transT[j * 33 + p * 4 + 1];
            float v2 = s4.z + transT[j * 33 + p * 4 + 2];
            float v3 = s4.w + transT[j * 33 + p * 4 + 3];
            bool t01 = v1 > v0; m0 = t01 ? v1 : v0; a0 = t01 ? p * 4 + 1 : p * 4;
            bool t23 = v3 > v2; m1 = t23 ? v3 : v2; a1 = t23 ? p * 4 + 3 : p * 4 + 2;
            bool tq = m1 > m0; float mq = tq ? m1 : m0; int aq = tq ? a1 : a0;
            bool tb = mq > bestv;
            bestv = tb ? mq : bestv;
            besta = tb ? aq : besta;
        }
        float nscore = bestv + e;
        bool msk = (t < len);
        hist[t - 1][j] = (unsigned char)(msk ? besta : j);
        score = msk ? nscore : score;
        __syncwarp();
    }
    score += endt[j];

    float bvv = score; int bii = j;
#pragma unroll
    for (int off = 16; off; off >>= 1) {
        float ov = __shfl_xor_sync(0xffffffffu, bvv, off);
        int   oi = __shfl_xor_sync(0xffffffffu, bii, off);
        if (ov > bvv || (ov == bvv && oi < bii)) { bvv = ov; bii = oi; }
    }
    __syncwarp();

    if (write_preds && j == 0) {
        int tag = bii;
        float* pp = preds + (size_t)b * SEQ;
        for (int t = SEQ - 2; t >= 0; t--) {
            pp[t + 1] = (float)(((t + 1) < len) ? tag : 0);
            tag = hist[t][tag];
        }
        pp[0] = (float)((0 < len) ? tag : 0);
    }
}

// ---------------- launch ----------------
extern "C" void kernel_launch(void* const* d_in, const int* in_sizes, int n_in,
                              void* d_out, int out_size)
{
    const float* x     = (const float*)d_in[0];
    const int*   lens  = (const int*)d_in[1];
    const float* Wih_f = (const float*)d_in[3];
    const float* Whh_f = (const float*)d_in[4];
    const float* b_f   = (const float*)d_in[5];
    const float* Wih_b = (const float*)d_in[6];
    const float* Whh_b = (const float*)d_in[7];
    const float* b_b   = (const float*)d_in[8];
    const float* W_clf = (const float*)d_in[9];
    const float* b_clf = (const float*)d_in[10];
    const float* st_t  = (const float*)d_in[11];
    const float* en_t  = (const float*)d_in[12];
    const float* trans = (const float*)d_in[13];
    float* out = (float*)d_out;

    __nv_bfloat16 *xhi, *xlo, *whi, *wlo;
    cudaGetSymbolAddress((void**)&xhi, g_xhi);
    cudaGetSymbolAddress((void**)&xlo, g_xlo);
    cudaGetSymbolAddress((void**)&whi, g_whi);
    cudaGetSymbolAddress((void**)&wlo, g_wlo);

    const int fused_smem = 95232;
    cudaFuncSetAttribute(fused_kernel, cudaFuncAttributeMaxDynamicSharedMemorySize, fused_smem);

    split_kernel<<<2048, 256>>>((const float4*)x, (uint2*)xhi, (uint2*)xlo, 32768 * 512 / 4);
    split_kernel<<<128, 256>>>((const float4*)Wih_f, (uint2*)whi, (uint2*)wlo, 1024 * 512 / 4);
    split_kernel<<<128, 256>>>((const float4*)Wih_b,
                               (uint2*)(whi + (size_t)1024 * 512),
                               (uint2*)(wlo + (size_t)1024 * 512), 1024 * 512 / 4);

    reset_counters_kernel<<<1, 256>>>();
    fused_kernel<<<4224, 256, fused_smem>>>(b_f, b_b, Whh_f, Whh_b, lens);

    clf_kernel<<<512, 256>>>(W_clf, b_clf, out);

    const int logits_elems = BATCH * SEQ * NK;      // 1048576
    const int preds_elems  = BATCH * SEQ;           // 32768
    int wp = (out_size >= logits_elems + preds_elems) ? 1 : 0;
    viterbi_kernel<<<64, 32>>>(out, lens, st_t, en_t, trans, out + logits_elems, wp);
}

// round 16
// speedup vs baseline: 1.0497x; 1.0497x over previous
#include <cuda_runtime.h>
#include <cuda_bf16.h>
#include <cstdint>
#include <cstddef>

#define BATCH 64
#define SEQ   512
#define DIM   512
#define HID   256
#define NK    32

typedef unsigned long long u64;

// ---------------- scratch (__device__ globals; no allocation) ----------------
// xp layout: [t*64+b][g]  ((t*64+b)*2048 + g)
__device__ float g_xp[(size_t)SEQ * BATCH * 2048];          // 256 MiB
__device__ float g_hout[(size_t)2 * SEQ * HID * BATCH];     // 64 MiB:  [dir][t][j][b]
__device__ __nv_bfloat16 g_hhi[2 * 2 * BATCH * HID];        // [dir][buf][b][k] bf16 hi
__device__ __nv_bfloat16 g_hlo[2 * 2 * BATCH * HID];        // [dir][buf][b][k] bf16 lo
__device__ __nv_bfloat16 g_xhi[(size_t)32768 * 512];
__device__ __nv_bfloat16 g_xlo[(size_t)32768 * 512];
__device__ __nv_bfloat16 g_whi[(size_t)2048 * 512];
__device__ __nv_bfloat16 g_wlo[(size_t)2048 * 512];
__device__ unsigned g_gcnt[8 * 32];                         // 8 group counters, 128B apart

// ---------------- mma.sync / ldmatrix / cp.async helpers ----------------
__device__ __forceinline__ uint32_t smem_to_u32(const void* p) {
    uint32_t a;
    asm("{ .reg .u64 t; cvta.to.shared.u64 t, %1; cvt.u32.u64 %0, t; }" : "=r"(a) : "l"(p));
    return a;
}
__device__ __forceinline__ void cp_async16(uint32_t saddr, const void* gptr) {
    asm volatile("cp.async.cg.shared.global [%0], [%1], 16;" :: "r"(saddr), "l"(gptr));
}
#define CP_COMMIT() asm volatile("cp.async.commit_group;")
#define CP_WAIT(n)  asm volatile("cp.async.wait_group %0;" :: "n"(n) : "memory")

__device__ __forceinline__ void ldsm4(uint32_t* r, uint32_t addr) {
    asm volatile("ldmatrix.sync.aligned.m8n8.x4.shared.b16 {%0,%1,%2,%3}, [%4];"
        : "=r"(r[0]), "=r"(r[1]), "=r"(r[2]), "=r"(r[3]) : "r"(addr));
}
__device__ __forceinline__ void ldsm2(uint32_t* r, uint32_t addr) {
    asm volatile("ldmatrix.sync.aligned.m8n8.x2.shared.b16 {%0,%1}, [%2];"
        : "=r"(r[0]), "=r"(r[1]) : "r"(addr));
}
__device__ __forceinline__ void mma16816(float* c, const uint32_t* a, uint32_t b0, uint32_t b1) {
    asm volatile("mma.sync.aligned.m16n8k16.row.col.f32.bf16.bf16.f32 "
        "{%0,%1,%2,%3}, {%4,%5,%6,%7}, {%8,%9}, {%0,%1,%2,%3};"
        : "+f"(c[0]), "+f"(c[1]), "+f"(c[2]), "+f"(c[3])
        : "r"(a[0]), "r"(a[1]), "r"(a[2]), "r"(a[3]), "r"(b0), "r"(b1));
}

// ---------------- group barrier (16 CTAs, monotonic, split arrive/wait) -----
__device__ __forceinline__ void barrier_arrive(unsigned* cnt)
{
    __syncthreads();
    if (threadIdx.x == 0)
        asm volatile("red.release.gpu.add.u32 [%0], 1;" :: "l"(cnt) : "memory");
}
__device__ __forceinline__ void barrier_wait(unsigned* cnt, unsigned target)
{
    if (threadIdx.x == 0) {
        unsigned v;
        while (true) {
            asm volatile("ld.acquire.gpu.u32 %0, [%1];" : "=r"(v) : "l"(cnt) : "memory");
            if (v >= target) break;
            __nanosleep(20);
        }
    }
    __syncthreads();
}

// ---------------- Kernel 0: fp32 -> bf16 hi/lo split (vectorized) -----------
// do_reset: block 0 also zeroes the LSTM group counters (runs before lstm).
__global__ __launch_bounds__(256) void split_kernel(
    const float4* __restrict__ src, uint2* __restrict__ hi,
    uint2* __restrict__ lo, int n4, int do_reset)
{
    if (do_reset && blockIdx.x == 0 && threadIdx.x < 8 * 32)
        g_gcnt[threadIdx.x] = 0;
    int stride = gridDim.x * blockDim.x;
    for (int i = blockIdx.x * blockDim.x + threadIdx.x; i < n4; i += stride) {
        float4 v = src[i];
        __nv_bfloat16 hx = __float2bfloat16(v.x);
        __nv_bfloat16 hy = __float2bfloat16(v.y);
        __nv_bfloat16 hz = __float2bfloat16(v.z);
        __nv_bfloat16 hw = __float2bfloat16(v.w);
        __nv_bfloat16 lx = __float2bfloat16(v.x - __bfloat162float(hx));
        __nv_bfloat16 ly = __float2bfloat16(v.y - __bfloat162float(hy));
        __nv_bfloat16 lz = __float2bfloat16(v.z - __bfloat162float(hz));
        __nv_bfloat16 lw = __float2bfloat16(v.w - __bfloat162float(hw));
        uint2 H, L;
        H.x = (uint32_t)__bfloat16_as_ushort(hx) | ((uint32_t)__bfloat16_as_ushort(hy) << 16);
        H.y = (uint32_t)__bfloat16_as_ushort(hz) | ((uint32_t)__bfloat16_as_ushort(hw) << 16);
        L.x = (uint32_t)__bfloat16_as_ushort(lx) | ((uint32_t)__bfloat16_as_ushort(ly) << 16);
        L.y = (uint32_t)__bfloat16_as_ushort(lz) | ((uint32_t)__bfloat16_as_ushort(lw) << 16);
        hi[i] = H; lo[i] = L;
    }
}

// ---------------- Kernel 1: bf16 3-split GEMM, 3-stage cp.async pipeline ----
#define NCHUNK 32
__global__ __launch_bounds__(256) void gemm_xp_mma_kernel(
    const float* __restrict__ bf_, const float* __restrict__ bb_)
{
    extern __shared__ __align__(128) char dsm[];   // 3 stages x 16384 B
    __shared__ float s_bias[128];

    const int tid  = threadIdx.x;
    const int lane = tid & 31;
    const int wid  = tid >> 5;
    const int wm   = wid >> 2;
    const int wn   = wid & 3;
    const int nTile = blockIdx.x;
    const int mTile = blockIdx.y;
    const int mBase = mTile * 128;
    const int nBase = nTile * 128;

    if (tid < 128) {
        const float* bsrc = (nTile < 8) ? bf_ : bb_;
        int boff = (nTile < 8) ? nTile * 128 : (nTile - 8) * 128;
        s_bias[tid] = bsrc[boff + tid];
    }

    const uint32_t smem_base = smem_to_u32(dsm);

    uint32_t aoff[2][4];
    {
        const int arow = wm * 64 + (lane & 15);
        const int akc  = lane >> 4;
#pragma unroll
        for (int mf = 0; mf < 4; mf++) {
            const int r = arow + mf * 16;
            const uint32_t o = (uint32_t)(r * 32 + ((akc ^ ((r >> 2) & 1)) << 4));
            aoff[0][mf] = o;
            aoff[1][mf] = o + 4096u;
        }
    }
    uint32_t boff[2][2];
    {
        const int nrow = wn * 32 + (lane & 7) + ((lane >> 4) << 3);
        const int bkc  = (lane >> 3) & 1;
#pragma unroll
        for (int p = 0; p < 2; p++) {
            const int r = nrow + p * 16;
            const uint32_t o = (uint32_t)(r * 32 + ((bkc ^ ((r >> 2) & 1)) << 4));
            boff[0][p] = o + 8192u;
            boff[1][p] = o + 12288u;
        }
    }

    const int ldrow = tid >> 1;
    const int ldck  = tid & 1;
    const uint32_t ld_soff = (uint32_t)(ldrow * 32 + ((ldck ^ ((ldrow >> 2) & 1)) << 4));
    const __nv_bfloat16* Ahg = g_xhi + (size_t)(mBase + ldrow) * 512 + ldck * 8;
    const __nv_bfloat16* Alg = g_xlo + (size_t)(mBase + ldrow) * 512 + ldck * 8;
    const __nv_bfloat16* Bhg = g_whi + (size_t)(nBase + ldrow) * 512 + ldck * 8;
    const __nv_bfloat16* Blg = g_wlo + (size_t)(nBase + ldrow) * 512 + ldck * 8;

    float cr[4][4][4];
#pragma unroll
    for (int mf = 0; mf < 4; mf++)
#pragma unroll
        for (int nf = 0; nf < 4; nf++)
#pragma unroll
            for (int q = 0; q < 4; q++) cr[mf][nf][q] = 0.f;

#pragma unroll
    for (int s = 0; s < 2; s++) {
        const int kb = s * 16;
        const uint32_t so = smem_base + s * 16384u + ld_soff;
        cp_async16(so,          Ahg + kb);
        cp_async16(so + 4096u,  Alg + kb);
        cp_async16(so + 8192u,  Bhg + kb);
        cp_async16(so + 12288u, Blg + kb);
        CP_COMMIT();
    }

    int cb = 0;   // compute stage
    int ib = 2;   // issue stage
    for (int c = 0; c < NCHUNK; c++) {
        if (c + 1 < NCHUNK) { CP_WAIT(1); } else { CP_WAIT(0); }
        __syncthreads();

        if (c + 2 < NCHUNK) {
            const int kb = (c + 2) * 16;
            const uint32_t so = smem_base + ib * 16384u + ld_soff;
            cp_async16(so,          Ahg + kb);
            cp_async16(so + 4096u,  Alg + kb);
            cp_async16(so + 8192u,  Bhg + kb);
            cp_async16(so + 12288u, Blg + kb);
            CP_COMMIT();
        }

        const uint32_t stg = smem_base + cb * 16384u;

        uint32_t ah[4][4];
#pragma unroll
        for (int mf = 0; mf < 4; mf++) ldsm4(ah[mf], stg + aoff[0][mf]);
        uint32_t bh[2][4];
#pragma unroll
        for (int p = 0; p < 2; p++) ldsm4(bh[p], stg + boff[0][p]);
#pragma unroll
        for (int mf = 0; mf < 4; mf++)
#pragma unroll
            for (int nf = 0; nf < 4; nf++)
                mma16816(cr[mf][nf], ah[mf], bh[nf >> 1][2 * (nf & 1)], bh[nf >> 1][2 * (nf & 1) + 1]);

        uint32_t bl[2][4];
#pragma unroll
        for (int p = 0; p < 2; p++) ldsm4(bl[p], stg + boff[1][p]);
#pragma unroll
        for (int mf = 0; mf < 4; mf++)
#pragma unroll
            for (int nf = 0; nf < 4; nf++)
                mma16816(cr[mf][nf], ah[mf], bl[nf >> 1][2 * (nf & 1)], bl[nf >> 1][2 * (nf & 1) + 1]);

        uint32_t al[4][4];
#pragma unroll
        for (int mf = 0; mf < 4; mf++) ldsm4(al[mf], stg + aoff[1][mf]);
#pragma unroll
        for (int mf = 0; mf < 4; mf++)
#pragma unroll
            for (int nf = 0; nf < 4; nf++)
                mma16816(cr[mf][nf], al[mf], bh[nf >> 1][2 * (nf & 1)], bh[nf >> 1][2 * (nf & 1) + 1]);

        cb = (cb == 2) ? 0 : cb + 1;
        ib = (ib == 2) ? 0 : ib + 1;
    }

#pragma unroll
    for (int mf = 0; mf < 4; mf++) {
        const int m0 = mBase + wm * 64 + mf * 16 + (lane >> 2);
        const int m1 = m0 + 8;
        const size_t r0 = ((size_t)(m0 & 511) * 64 + (m0 >> 9)) * 2048;
        const size_t r1 = ((size_t)(m1 & 511) * 64 + (m1 >> 9)) * 2048;
#pragma unroll
        for (int nf = 0; nf < 4; nf++) {
            const int nl = wn * 32 + nf * 8 + (lane & 3) * 2;
            const float b0 = s_bias[nl], b1 = s_bias[nl + 1];
            const int n = nBase + nl;
            float2 v0 = make_float2(cr[mf][nf][0] + b0, cr[mf][nf][1] + b1);
            float2 v1 = make_float2(cr[mf][nf][2] + b0, cr[mf][nf][3] + b1);
            *(float2*)&g_xp[r0 + n] = v0;
            *(float2*)&g_xp[r1 + n] = v1;
        }
    }
}

// ---------------- Kernel 2: persistent biLSTM recurrence (tensor-core) ------
__global__ __launch_bounds__(256) void lstm_kernel(
    const float* __restrict__ Whh_f, const float* __restrict__ Whh_b,
    const int* __restrict__ lengths)
{
    extern __shared__ __align__(16) char dynb[];
    char*  smWh = dynb;                       // 32768
    char*  smWl = dynb + 32768;               // 32768
    char*  smHh = dynb + 65536;               // 8192
    char*  smHl = dynb + 73728;               // 8192
    float* gsm  = (float*)(dynb + 81920);     // 64*18 floats
    float* xsm  = (float*)(dynb + 86528);     // 2*1088 floats

    const int tid = threadIdx.x;
    const int cta = blockIdx.x;
    const int dir = cta >> 6;
    const int s   = (cta >> 2) & 15;
    const int gb  = cta & 3;
    const int s16   = s * 16;
    const int bbase = gb * 16;
    const float* Whh = dir ? Whh_b : Whh_f;
    unsigned* gcnt = &g_gcnt[(dir * 4 + gb) * 32];

    for (int idx = tid; idx < 64 * 256; idx += 256) {
        int r = idx >> 8, k = idx & 255;
        int q = r >> 4, jj = r & 15;
        float wv = Whh[(q * 256 + s16 + jj) * 256 + k];
        __nv_bfloat16 hi = __float2bfloat16(wv);
        __nv_bfloat16 lo = __float2bfloat16(wv - __bfloat162float(hi));
        int kc = k >> 3, ko = k & 7;
        int off = r * 512 + ((kc ^ (r & 7)) << 4) + ko * 2;
        *(__nv_bfloat16*)(smWh + off) = hi;
        *(__nv_bfloat16*)(smWl + off) = lo;
    }

    const int j = tid >> 4;
    const int b = tid & 15;
    const int len_b = lengths[bbase + b];

    {
        size_t o = ((size_t)(dir * 2 + 0) * 64 + bbase + b) * 256 + s16 + j;
        g_hhi[o] = __float2bfloat16(0.f);
        g_hlo[o] = __float2bfloat16(0.f);
    }

    const uint32_t xsm_addr = smem_to_u32(xsm);
    const uint32_t hh_addr  = smem_to_u32(smHh);
    const uint32_t hl_addr  = smem_to_u32(smHl);
    const uint32_t wh_addr  = smem_to_u32(smWh);
    const uint32_t wl_addr  = smem_to_u32(smWl);

    {
        const int t0 = dir ? (SEQ - 1) : 0;
        const int r = tid >> 2, c = tid & 3;
        const int pb = r >> 2, pq = r & 3;
        cp_async16(xsm_addr + (uint32_t)((pb * 68 + pq * 16 + c * 4) * 4),
                   &g_xp[((size_t)t0 * 64 + bbase + pb) * 2048 + dir * 1024 + pq * 256 + s16 + c * 4]);
        CP_COMMIT();
    }
    barrier_arrive(gcnt);
    barrier_wait(gcnt, 16u);

    const int lane = tid & 31;
    const int wrp  = tid >> 5;
    const int mf   = wrp >> 1;
    const int nb8  = wrp & 1;
    const int rowA = mf * 16 + (lane & 15);
    const int halfA = lane >> 4;
    const int rowB = nb8 * 8 + (lane & 7);
    const int halfB = (lane >> 3) & 1;

    float c_st = 0.f, h_st = 0.f;

    for (int st = 0; st < SEQ; st++) {
        const int tstep = dir ? (SEQ - 1 - st) : st;
        const int cur   = st & 1;
        const int gbuf  = st & 1;

        {
            const __nv_bfloat16* shi = g_hhi + (size_t)(dir * 2 + gbuf) * 64 * 256;
            const __nv_bfloat16* slo = g_hlo + (size_t)(dir * 2 + gbuf) * 64 * 256;
#pragma unroll
            for (int r2 = 0; r2 < 2; r2++) {
                int cch = tid + r2 * 256;
                int n = cch >> 5, kc = cch & 31;
                uint32_t so = (uint32_t)(n * 512 + ((kc ^ (n & 7)) << 4));
                cp_async16(hh_addr + so, shi + (size_t)(bbase + n) * 256 + kc * 8);
                cp_async16(hl_addr + so, slo + (size_t)(bbase + n) * 256 + kc * 8);
            }
            CP_COMMIT();
        }
        CP_WAIT(0);
        __syncthreads();

        if (st + 1 < SEQ) {
            const int tn = dir ? (SEQ - 2 - st) : (st + 1);
            const int r = tid >> 2, c = tid & 3;
            const int pb = r >> 2, pq = r & 3;
            cp_async16(xsm_addr + (uint32_t)(((cur ^ 1) * 1088 + pb * 68 + pq * 16 + c * 4) * 4),
                       &g_xp[((size_t)tn * 64 + bbase + pb) * 2048 + dir * 1024 + pq * 256 + s16 + c * 4]);
            CP_COMMIT();
        }

        float chh0[4] = {0,0,0,0}, chh1[4] = {0,0,0,0};
        float chl0[4] = {0,0,0,0}, chl1[4] = {0,0,0,0};
        float clh0[4] = {0,0,0,0}, clh1[4] = {0,0,0,0};
#pragma unroll
        for (int ks = 0; ks < 16; ks++) {
            const int kcA = ks * 2 + halfA;
            const uint32_t offA = (uint32_t)(rowA * 512 + ((kcA ^ (rowA & 7)) << 4));
            const int kcB = ks * 2 + halfB;
            const uint32_t offB = (uint32_t)(rowB * 512 + ((kcB ^ (rowB & 7)) << 4));
            uint32_t ah[4], al[4], bhp[2], blp[2];
            ldsm4(ah, wh_addr + offA);
            ldsm4(al, wl_addr + offA);
            ldsm2(bhp, hh_addr + offB);
            ldsm2(blp, hl_addr + offB);
            if (ks & 1) {
                mma16816(chh1, ah, bhp[0], bhp[1]);
                mma16816(chl1, ah, blp[0], blp[1]);
                mma16816(clh1, al, bhp[0], bhp[1]);
            } else {
                mma16816(chh0, ah, bhp[0], bhp[1]);
                mma16816(chl0, ah, blp[0], blp[1]);
                mma16816(clh0, al, bhp[0], bhp[1]);
            }
        }
        {
            const int r0  = mf * 16 + (lane >> 2);
            const int col = nb8 * 8 + 2 * (lane & 3);
            float2 v0 = make_float2(chh0[0] + chh1[0] + chl0[0] + chl1[0] + clh0[0] + clh1[0],
                                    chh0[1] + chh1[1] + chl0[1] + chl1[1] + clh0[1] + clh1[1]);
            float2 v1 = make_float2(chh0[2] + chh1[2] + chl0[2] + chl1[2] + clh0[2] + clh1[2],
                                    chh0[3] + chh1[3] + chl0[3] + chl1[3] + clh0[3] + clh1[3]);
            *(float2*)&gsm[r0 * 18 + col]       = v0;
            *(float2*)&gsm[(r0 + 8) * 18 + col] = v1;
        }
        __syncthreads();

        {
            const float* xq = xsm + cur * 1088 + b * 68;
            float a0 = gsm[(0 * 16 + j) * 18 + b] + xq[0 * 16 + j];
            float a1 = gsm[(1 * 16 + j) * 18 + b] + xq[1 * 16 + j];
            float a2 = gsm[(2 * 16 + j) * 18 + b] + xq[2 * 16 + j];
            float a3 = gsm[(3 * 16 + j) * 18 + b] + xq[3 * 16 + j];
            float i_ = __fdividef(1.f, 1.f + __expf(-a0));
            float f_ = __fdividef(1.f, 1.f + __expf(-a1));
            float g_ = tanhf(a2);
            float o_ = __fdividef(1.f, 1.f + __expf(-a3));
            float c_new = f_ * c_st + i_ * g_;
            float h_new = o_ * tanhf(c_new);
            bool  m = (tstep < len_b);
            c_st = m ? c_new : c_st;
            h_st = m ? h_new : h_st;
            __nv_bfloat16 hh = __float2bfloat16(h_st);
            __nv_bfloat16 hl = __float2bfloat16(h_st - __bfloat162float(hh));
            size_t o = ((size_t)(dir * 2 + (gbuf ^ 1)) * 64 + bbase + b) * 256 + s16 + j;
            g_hhi[o] = hh;
            g_hlo[o] = hl;
        }
        barrier_arrive(gcnt);
        g_hout[((size_t)(dir * SEQ + tstep) * HID + (s16 + j)) * 64 + bbase + b] = h_st;
        barrier_wait(gcnt, 16u * (st + 2));
    }
}

// ---------------- Kernel 3: logits = [h_f;h_b] @ W_clf^T + b_clf ----------------
__global__ __launch_bounds__(256) void clf_kernel(
    const float* __restrict__ Wclf, const float* __restrict__ bclf,
    float* __restrict__ out)
{
    __shared__ float Ws[32 * 65];
    __shared__ __align__(16) float hs[64 * 64];
    const int t   = blockIdx.x;
    const int tid = threadIdx.x;
    const int n   = tid & 31;
    const int bg  = tid >> 5;

    float acc[8];
#pragma unroll
    for (int i = 0; i < 8; i++) acc[i] = 0.f;

    for (int ch = 0; ch < 8; ch++) {
        const int dir = ch >> 2;
        const int jbase = (ch & 3) * 64;
        for (int l = tid; l < 2048; l += 256) {
            int nn = l >> 6, jj = l & 63;
            Ws[nn * 65 + jj] = Wclf[nn * 512 + dir * 256 + jbase + jj];
        }
        const float* hsrc = g_hout + ((size_t)(dir * SEQ + t) * HID + jbase) * 64;
#pragma unroll
        for (int r = 0; r < 4; r++)
            ((float4*)hs)[tid + r * 256] = __ldg(((const float4*)hsrc) + tid + r * 256);
        __syncthreads();
#pragma unroll 16
        for (int jj = 0; jj < 64; jj++) {
            float wv = Ws[n * 65 + jj];
            float4 hA = *(const float4*)&hs[jj * 64 + bg * 8];
            float4 hB = *(const float4*)&hs[jj * 64 + bg * 8 + 4];
            acc[0] += wv * hA.x; acc[1] += wv * hA.y; acc[2] += wv * hA.z; acc[3] += wv * hA.w;
            acc[4] += wv * hB.x; acc[5] += wv * hB.y; acc[6] += wv * hB.z; acc[7] += wv * hB.w;
        }
        __syncthreads();
    }
    const float bias = bclf[n];
#pragma unroll
    for (int bb = 0; bb < 8; bb++) {
        int b = bg * 8 + bb;
        out[((size_t)b * SEQ + t) * NK + n] = acc[bb] + bias;
    }
}

// ---------------- Kernel 4: Viterbi decode (smem-based) ----------------
__global__ __launch_bounds__(32) void viterbi_kernel(
    const float* __restrict__ logits, const int* __restrict__ lengths,
    const float* __restrict__ startt, const float* __restrict__ endt,
    const float* __restrict__ trans, float* __restrict__ preds, int write_preds)
{
    __shared__ float transT[32 * 33];
    __shared__ float sscore[2][32];
    __shared__ unsigned char hist[511][32];
    const int b = blockIdx.x;
    const int j = threadIdx.x;
    const int len = lengths[b];

#pragma unroll 4
    for (int i = 0; i < 32; i++) transT[j * 33 + i] = trans[i * 32 + j];

    const float* lg = logits + (size_t)b * SEQ * NK;
    float score = startt[j] + lg[j];
    float e_next = lg[NK + j];

    for (int t = 1; t < SEQ; t++) {
        const int buf = t & 1;
        sscore[buf][j] = score;
        __syncwarp();
        float e = e_next;
        if (t + 1 < SEQ) e_next = lg[(t + 1) * NK + j];

        float m0, m1; int a0, a1;
        float bestv = -3.4e38f; int besta = 0;
#pragma unroll
        for (int p = 0; p < 8; p++) {
            float4 s4 = *(const float4*)&sscore[buf][p * 4];
            float v0 = s4.x + transT[j * 33 + p * 4 + 0];
            float v1 = s4.y + transT[j * 33 + p * 4 + 1];
            float v2 = s4.z + transT[j * 33 + p * 4 + 2];
            float v3 = s4.w + transT[j * 33 + p * 4 + 3];
            bool t01 = v1 > v0; m0 = t01 ? v1 : v0; a0 = t01 ? p * 4 + 1 : p * 4;
            bool t23 = v3 > v2; m1 = t23 ? v3 : v2; a1 = t23 ? p * 4 + 3 : p * 4 + 2;
            bool tq = m1 > m0; float mq = tq ? m1 : m0; int aq = tq ? a1 : a0;
            bool tb = mq > bestv;
            bestv = tb ? mq : bestv;
            besta = tb ? aq : besta;
        }
        float nscore = bestv + e;
        bool msk = (t < len);
        hist[t - 1][j] = (unsigned char)(msk ? besta : j);
        score = msk ? nscore : score;
        __syncwarp();
    }
    score += endt[j];

    float bvv = score; int bii = j;
#pragma unroll
    for (int off = 16; off; off >>= 1) {
        float ov = __shfl_xor_sync(0xffffffffu, bvv, off);
        int   oi = __shfl_xor_sync(0xffffffffu, bii, off);
        if (ov > bvv || (ov == bvv && oi < bii)) { bvv = ov; bii = oi; }
    }
    __syncwarp();

    if (write_preds && j == 0) {
        int tag = bii;
        float* pp = preds + (size_t)b * SEQ;
        for (int t = SEQ - 2; t >= 0; t--) {
            pp[t + 1] = (float)(((t + 1) < len) ? tag : 0);
            tag = hist[t][tag];
        }
        pp[0] = (float)((0 < len) ? tag : 0);
    }
}

// ---------------- launch ----------------
extern "C" void kernel_launch(void* const* d_in, const int* in_sizes, int n_in,
                              void* d_out, int out_size)
{
    const float* x     = (const float*)d_in[0];
    const int*   lens  = (const int*)d_in[1];
    const float* Wih_f = (const float*)d_in[3];
    const float* Whh_f = (const float*)d_in[4];
    const float* b_f   = (const float*)d_in[5];
    const float* Wih_b = (const float*)d_in[6];
    const float* Whh_b = (const float*)d_in[7];
    const float* b_b   = (const float*)d_in[8];
    const float* W_clf = (const float*)d_in[9];
    const float* b_clf = (const float*)d_in[10];
    const float* st_t  = (const float*)d_in[11];
    const float* en_t  = (const float*)d_in[12];
    const float* trans = (const float*)d_in[13];
    float* out = (float*)d_out;

    __nv_bfloat16 *xhi, *xlo, *whi, *wlo;
    cudaGetSymbolAddress((void**)&xhi, g_xhi);
    cudaGetSymbolAddress((void**)&xlo, g_xlo);
    cudaGetSymbolAddress((void**)&whi, g_whi);
    cudaGetSymbolAddress((void**)&wlo, g_wlo);

    const int lstm_smem = 95232;
    cudaFuncSetAttribute(lstm_kernel, cudaFuncAttributeMaxDynamicSharedMemorySize, lstm_smem);
    const int gemm_smem = 3 * 16384;
    cudaFuncSetAttribute(gemm_xp_mma_kernel, cudaFuncAttributeMaxDynamicSharedMemorySize, gemm_smem);

    split_kernel<<<2048, 256>>>((const float4*)x, (uint2*)xhi, (uint2*)xlo, 32768 * 512 / 4, 1);
    split_kernel<<<128, 256>>>((const float4*)Wih_f, (uint2*)whi, (uint2*)wlo, 1024 * 512 / 4, 0);
    split_kernel<<<128, 256>>>((const float4*)Wih_b,
                               (uint2*)(whi + (size_t)1024 * 512),
                               (uint2*)(wlo + (size_t)1024 * 512), 1024 * 512 / 4, 0);

    gemm_xp_mma_kernel<<<dim3(16, 256), 256, gemm_smem>>>(b_f, b_b);

    lstm_kernel<<<128, 256, lstm_smem>>>(Whh_f, Whh_b, lens);
    clf_kernel<<<512, 256>>>(W_clf, b_clf, out);

    const int logits_elems = BATCH * SEQ * NK;      // 1048576
    const int preds_elems  = BATCH * SEQ;           // 32768
    int wp = (out_size >= logits_elems + preds_elems) ? 1 : 0;
    viterbi_kernel<<<64, 32>>>(out, lens, st_t, en_t, trans, out + logits_elems, wp);
}

// round 17
// speedup vs baseline: 1.0976x; 1.0456x over previous
#include <cuda_runtime.h>
#include <cuda_bf16.h>
#include <cstdint>
#include <cstddef>

#define BATCH 64
#define SEQ   512
#define DIM   512
#define HID   256
#define NK    32

typedef unsigned long long u64;

// ---------------- scratch (__device__ globals; no allocation) ----------------
// xp layout: [t*64+b][g]  ((t*64+b)*2048 + g)
__device__ float g_xp[(size_t)SEQ * BATCH * 2048];          // 256 MiB
__device__ float g_hout[(size_t)2 * SEQ * HID * BATCH];     // 64 MiB:  [dir][t][j][b]
__device__ __nv_bfloat16 g_hhi[2 * 2 * BATCH * HID];        // [dir][buf][b][k] bf16 hi
__device__ __nv_bfloat16 g_hlo[2 * 2 * BATCH * HID];        // [dir][buf][b][k] bf16 lo
__device__ __nv_bfloat16 g_xhi[(size_t)32768 * 512];
__device__ __nv_bfloat16 g_xlo[(size_t)32768 * 512];
__device__ __nv_bfloat16 g_whi[(size_t)2048 * 512];
__device__ __nv_bfloat16 g_wlo[(size_t)2048 * 512];
__device__ unsigned g_gcnt[8 * 32];                         // 8 group counters, 128B apart

// ---------------- mma.sync / ldmatrix / cp.async helpers ----------------
__device__ __forceinline__ uint32_t smem_to_u32(const void* p) {
    uint32_t a;
    asm("{ .reg .u64 t; cvta.to.shared.u64 t, %1; cvt.u32.u64 %0, t; }" : "=r"(a) : "l"(p));
    return a;
}
__device__ __forceinline__ void cp_async16(uint32_t saddr, const void* gptr) {
    asm volatile("cp.async.cg.shared.global [%0], [%1], 16;" :: "r"(saddr), "l"(gptr));
}
#define CP_COMMIT() asm volatile("cp.async.commit_group;")
#define CP_WAIT(n)  asm volatile("cp.async.wait_group %0;" :: "n"(n) : "memory")

__device__ __forceinline__ void ldsm4(uint32_t* r, uint32_t addr) {
    asm volatile("ldmatrix.sync.aligned.m8n8.x4.shared.b16 {%0,%1,%2,%3}, [%4];"
        : "=r"(r[0]), "=r"(r[1]), "=r"(r[2]), "=r"(r[3]) : "r"(addr));
}
__device__ __forceinline__ void ldsm2(uint32_t* r, uint32_t addr) {
    asm volatile("ldmatrix.sync.aligned.m8n8.x2.shared.b16 {%0,%1}, [%2];"
        : "=r"(r[0]), "=r"(r[1]) : "r"(addr));
}
__device__ __forceinline__ void mma16816(float* c, const uint32_t* a, uint32_t b0, uint32_t b1) {
    asm volatile("mma.sync.aligned.m16n8k16.row.col.f32.bf16.bf16.f32 "
        "{%0,%1,%2,%3}, {%4,%5,%6,%7}, {%8,%9}, {%0,%1,%2,%3};"
        : "+f"(c[0]), "+f"(c[1]), "+f"(c[2]), "+f"(c[3])
        : "r"(a[0]), "r"(a[1]), "r"(a[2]), "r"(a[3]), "r"(b0), "r"(b1));
}

// ---------------- group barrier (16 CTAs, monotonic, split arrive/wait) -----
__device__ __forceinline__ void barrier_arrive(unsigned* cnt)
{
    __syncthreads();
    if (threadIdx.x == 0)
        asm volatile("red.release.gpu.add.u32 [%0], 1;" :: "l"(cnt) : "memory");
}
__device__ __forceinline__ void barrier_wait(unsigned* cnt, unsigned target)
{
    if (threadIdx.x == 0) {
        unsigned v;
        while (true) {
            asm volatile("ld.acquire.gpu.u32 %0, [%1];" : "=r"(v) : "l"(cnt) : "memory");
            if (v >= target) break;
            __nanosleep(20);
        }
    }
    __syncthreads();
}

// ---------------- Kernel 0: fp32 -> bf16 hi/lo split (vectorized) -----------
__global__ __launch_bounds__(256) void split_kernel(
    const float4* __restrict__ src, uint2* __restrict__ hi,
    uint2* __restrict__ lo, int n4, int do_reset)
{
    if (do_reset && blockIdx.x == 0 && threadIdx.x < 8 * 32)
        g_gcnt[threadIdx.x] = 0;
    int stride = gridDim.x * blockDim.x;
    for (int i = blockIdx.x * blockDim.x + threadIdx.x; i < n4; i += stride) {
        float4 v = src[i];
        __nv_bfloat16 hx = __float2bfloat16(v.x);
        __nv_bfloat16 hy = __float2bfloat16(v.y);
        __nv_bfloat16 hz = __float2bfloat16(v.z);
        __nv_bfloat16 hw = __float2bfloat16(v.w);
        __nv_bfloat16 lx = __float2bfloat16(v.x - __bfloat162float(hx));
        __nv_bfloat16 ly = __float2bfloat16(v.y - __bfloat162float(hy));
        __nv_bfloat16 lz = __float2bfloat16(v.z - __bfloat162float(hz));
        __nv_bfloat16 lw = __float2bfloat16(v.w - __bfloat162float(hw));
        uint2 H, L;
        H.x = (uint32_t)__bfloat16_as_ushort(hx) | ((uint32_t)__bfloat16_as_ushort(hy) << 16);
        H.y = (uint32_t)__bfloat16_as_ushort(hz) | ((uint32_t)__bfloat16_as_ushort(hw) << 16);
        L.x = (uint32_t)__bfloat16_as_ushort(lx) | ((uint32_t)__bfloat16_as_ushort(ly) << 16);
        L.y = (uint32_t)__bfloat16_as_ushort(lz) | ((uint32_t)__bfloat16_as_ushort(lw) << 16);
        hi[i] = H; lo[i] = L;
    }
}

// ---------------- Kernel 1: bf16 3-split GEMM, 3-stage cp.async pipeline ----
#define NCHUNK 32
__global__ __launch_bounds__(256) void gemm_xp_mma_kernel(
    const float* __restrict__ bf_, const float* __restrict__ bb_)
{
    extern __shared__ __align__(128) char dsm[];   // 3 stages x 16384 B
    __shared__ float s_bias[128];

    const int tid  = threadIdx.x;
    const int lane = tid & 31;
    const int wid  = tid >> 5;
    const int wm   = wid >> 2;
    const int wn   = wid & 3;
    const int nTile = blockIdx.x;
    const int mTile = blockIdx.y;
    const int mBase = mTile * 128;
    const int nBase = nTile * 128;

    if (tid < 128) {
        const float* bsrc = (nTile < 8) ? bf_ : bb_;
        int boff = (nTile < 8) ? nTile * 128 : (nTile - 8) * 128;
        s_bias[tid] = bsrc[boff + tid];
    }

    const uint32_t smem_base = smem_to_u32(dsm);

    uint32_t aoff[2][4];
    {
        const int arow = wm * 64 + (lane & 15);
        const int akc  = lane >> 4;
#pragma unroll
        for (int mf = 0; mf < 4; mf++) {
            const int r = arow + mf * 16;
            const uint32_t o = (uint32_t)(r * 32 + ((akc ^ ((r >> 2) & 1)) << 4));
            aoff[0][mf] = o;
            aoff[1][mf] = o + 4096u;
        }
    }
    uint32_t boff[2][2];
    {
        const int nrow = wn * 32 + (lane & 7) + ((lane >> 4) << 3);
        const int bkc  = (lane >> 3) & 1;
#pragma unroll
        for (int p = 0; p < 2; p++) {
            const int r = nrow + p * 16;
            const uint32_t o = (uint32_t)(r * 32 + ((bkc ^ ((r >> 2) & 1)) << 4));
            boff[0][p] = o + 8192u;
            boff[1][p] = o + 12288u;
        }
    }

    const int ldrow = tid >> 1;
    const int ldck  = tid & 1;
    const uint32_t ld_soff = (uint32_t)(ldrow * 32 + ((ldck ^ ((ldrow >> 2) & 1)) << 4));
    const __nv_bfloat16* Ahg = g_xhi + (size_t)(mBase + ldrow) * 512 + ldck * 8;
    const __nv_bfloat16* Alg = g_xlo + (size_t)(mBase + ldrow) * 512 + ldck * 8;
    const __nv_bfloat16* Bhg = g_whi + (size_t)(nBase + ldrow) * 512 + ldck * 8;
    const __nv_bfloat16* Blg = g_wlo + (size_t)(nBase + ldrow) * 512 + ldck * 8;

    float cr[4][4][4];
#pragma unroll
    for (int mf = 0; mf < 4; mf++)
#pragma unroll
        for (int nf = 0; nf < 4; nf++)
#pragma unroll
            for (int q = 0; q < 4; q++) cr[mf][nf][q] = 0.f;

#pragma unroll
    for (int s = 0; s < 2; s++) {
        const int kb = s * 16;
        const uint32_t so = smem_base + s * 16384u + ld_soff;
        cp_async16(so,          Ahg + kb);
        cp_async16(so + 4096u,  Alg + kb);
        cp_async16(so + 8192u,  Bhg + kb);
        cp_async16(so + 12288u, Blg + kb);
        CP_COMMIT();
    }

    int cb = 0;   // compute stage
    int ib = 2;   // issue stage
    for (int c = 0; c < NCHUNK; c++) {
        if (c + 1 < NCHUNK) { CP_WAIT(1); } else { CP_WAIT(0); }
        __syncthreads();

        if (c + 2 < NCHUNK) {
            const int kb = (c + 2) * 16;
            const uint32_t so = smem_base + ib * 16384u + ld_soff;
            cp_async16(so,          Ahg + kb);
            cp_async16(so + 4096u,  Alg + kb);
            cp_async16(so + 8192u,  Bhg + kb);
            cp_async16(so + 12288u, Blg + kb);
            CP_COMMIT();
        }

        const uint32_t stg = smem_base + cb * 16384u;

        uint32_t ah[4][4];
#pragma unroll
        for (int mf = 0; mf < 4; mf++) ldsm4(ah[mf], stg + aoff[0][mf]);
        uint32_t bh[2][4];
#pragma unroll
        for (int p = 0; p < 2; p++) ldsm4(bh[p], stg + boff[0][p]);
#pragma unroll
        for (int mf = 0; mf < 4; mf++)
#pragma unroll
            for (int nf = 0; nf < 4; nf++)
                mma16816(cr[mf][nf], ah[mf], bh[nf >> 1][2 * (nf & 1)], bh[nf >> 1][2 * (nf & 1) + 1]);

        uint32_t bl[2][4];
#pragma unroll
        for (int p = 0; p < 2; p++) ldsm4(bl[p], stg + boff[1][p]);
#pragma unroll
        for (int mf = 0; mf < 4; mf++)
#pragma unroll
            for (int nf = 0; nf < 4; nf++)
                mma16816(cr[mf][nf], ah[mf], bl[nf >> 1][2 * (nf & 1)], bl[nf >> 1][2 * (nf & 1) + 1]);

        uint32_t al[4][4];
#pragma unroll
        for (int mf = 0; mf < 4; mf++) ldsm4(al[mf], stg + aoff[1][mf]);
#pragma unroll
        for (int mf = 0; mf < 4; mf++)
#pragma unroll
            for (int nf = 0; nf < 4; nf++)
                mma16816(cr[mf][nf], al[mf], bh[nf >> 1][2 * (nf & 1)], bh[nf >> 1][2 * (nf & 1) + 1]);

        cb = (cb == 2) ? 0 : cb + 1;
        ib = (ib == 2) ? 0 : ib + 1;
    }

#pragma unroll
    for (int mf = 0; mf < 4; mf++) {
        const int m0 = mBase + wm * 64 + mf * 16 + (lane >> 2);
        const int m1 = m0 + 8;
        const size_t r0 = ((size_t)(m0 & 511) * 64 + (m0 >> 9)) * 2048;
        const size_t r1 = ((size_t)(m1 & 511) * 64 + (m1 >> 9)) * 2048;
#pragma unroll
        for (int nf = 0; nf < 4; nf++) {
            const int nl = wn * 32 + nf * 8 + (lane & 3) * 2;
            const float b0 = s_bias[nl], b1 = s_bias[nl + 1];
            const int n = nBase + nl;
            float2 v0 = make_float2(cr[mf][nf][0] + b0, cr[mf][nf][1] + b1);
            float2 v1 = make_float2(cr[mf][nf][2] + b0, cr[mf][nf][3] + b1);
            *(float2*)&g_xp[r0 + n] = v0;
            *(float2*)&g_xp[r1 + n] = v1;
        }
    }
}

// ---------------- Kernel 2: persistent biLSTM recurrence (tensor-core) ------
// R17: persistent Wh register fragments + split-K h staging (2 cp groups,
// mma first half overlaps second-half load).
__global__ __launch_bounds__(256) void lstm_kernel(
    const float* __restrict__ Whh_f, const float* __restrict__ Whh_b,
    const int* __restrict__ lengths)
{
    extern __shared__ __align__(16) char dynb[];
    char*  smWh = dynb;                       // 32768
    char*  smWl = dynb + 32768;               // 32768
    char*  smHh = dynb + 65536;               // 8192
    char*  smHl = dynb + 73728;               // 8192
    float* gsm  = (float*)(dynb + 81920);     // 64*18 floats
    float* xsm  = (float*)(dynb + 86528);     // 2*1088 floats

    const int tid = threadIdx.x;
    const int cta = blockIdx.x;
    const int dir = cta >> 6;
    const int s   = (cta >> 2) & 15;
    const int gb  = cta & 3;
    const int s16   = s * 16;
    const int bbase = gb * 16;
    const float* Whh = dir ? Whh_b : Whh_f;
    unsigned* gcnt = &g_gcnt[(dir * 4 + gb) * 32];

    for (int idx = tid; idx < 64 * 256; idx += 256) {
        int r = idx >> 8, k = idx & 255;
        int q = r >> 4, jj = r & 15;
        float wv = Whh[(q * 256 + s16 + jj) * 256 + k];
        __nv_bfloat16 hi = __float2bfloat16(wv);
        __nv_bfloat16 lo = __float2bfloat16(wv - __bfloat162float(hi));
        int kc = k >> 3, ko = k & 7;
        int off = r * 512 + ((kc ^ (r & 7)) << 4) + ko * 2;
        *(__nv_bfloat16*)(smWh + off) = hi;
        *(__nv_bfloat16*)(smWl + off) = lo;
    }

    const int j = tid >> 4;
    const int b = tid & 15;
    const int len_b = lengths[bbase + b];

    {
        size_t o = ((size_t)(dir * 2 + 0) * 64 + bbase + b) * 256 + s16 + j;
        g_hhi[o] = __float2bfloat16(0.f);
        g_hlo[o] = __float2bfloat16(0.f);
    }

    const uint32_t xsm_addr = smem_to_u32(xsm);
    const uint32_t hh_addr  = smem_to_u32(smHh);
    const uint32_t hl_addr  = smem_to_u32(smHl);
    const uint32_t wh_addr  = smem_to_u32(smWh);
    const uint32_t wl_addr  = smem_to_u32(smWl);

    // prologue xp prefetch (step 0 -> buf 0)
    {
        const int t0 = dir ? (SEQ - 1) : 0;
        const int r = tid >> 2, c = tid & 3;
        const int pb = r >> 2, pq = r & 3;
        cp_async16(xsm_addr + (uint32_t)((pb * 68 + pq * 16 + c * 4) * 4),
                   &g_xp[((size_t)t0 * 64 + bbase + pb) * 2048 + dir * 1024 + pq * 256 + s16 + c * 4]);
        CP_COMMIT();
    }
    barrier_arrive(gcnt);
    barrier_wait(gcnt, 16u);

    const int lane = tid & 31;
    const int wrp  = tid >> 5;
    const int mf   = wrp >> 1;
    const int nb8  = wrp & 1;
    const int rowA = mf * 16 + (lane & 15);
    const int halfA = lane >> 4;
    const int rowB = nb8 * 8 + (lane & 7);
    const int halfB = (lane >> 3) & 1;

    // persistent Wh fragments (weights constant across all steps)
    uint32_t whreg[16][4];
#pragma unroll
    for (int ks = 0; ks < 16; ks++) {
        const int kcA = ks * 2 + halfA;
        ldsm4(whreg[ks], wh_addr + (uint32_t)(rowA * 512 + ((kcA ^ (rowA & 7)) << 4)));
    }

    // split-K h staging addresses: thread -> row n = tid>>4, kc = (tid&15) / +16
    const int hn  = tid >> 4;
    const int hkA = tid & 15;
    const int hkB = hkA + 16;
    const uint32_t hsoA = (uint32_t)(hn * 512 + ((hkA ^ (hn & 7)) << 4));
    const uint32_t hsoB = (uint32_t)(hn * 512 + ((hkB ^ (hn & 7)) << 4));

    float c_st = 0.f, h_st = 0.f;

    for (int st = 0; st < SEQ; st++) {
        const int tstep = dir ? (SEQ - 1 - st) : st;
        const int cur   = st & 1;
        const int gbuf  = st & 1;

        // stage h bf16 hi/lo in two groups (kc 0..15, then 16..31)
        {
            const __nv_bfloat16* shi = g_hhi + (size_t)(dir * 2 + gbuf) * 64 * 256;
            const __nv_bfloat16* slo = g_hlo + (size_t)(dir * 2 + gbuf) * 64 * 256;
            const size_t gro = (size_t)(bbase + hn) * 256;
            cp_async16(hh_addr + hsoA, shi + gro + hkA * 8);
            cp_async16(hl_addr + hsoA, slo + gro + hkA * 8);
            CP_COMMIT();
            cp_async16(hh_addr + hsoB, shi + gro + hkB * 8);
            cp_async16(hl_addr + hsoB, slo + gro + hkB * 8);
            CP_COMMIT();
        }
        CP_WAIT(1);        // xp(st) + group A complete
        __syncthreads();

        float chh0[4] = {0,0,0,0}, chh1[4] = {0,0,0,0};
        float chl0[4] = {0,0,0,0}, chl1[4] = {0,0,0,0};
        float clh0[4] = {0,0,0,0}, clh1[4] = {0,0,0,0};

        // mma first half: ks 0..7 (kc 0..15 resident)
#pragma unroll
        for (int ks = 0; ks < 8; ks++) {
            const int kcA = ks * 2 + halfA;
            const uint32_t offA = (uint32_t)(rowA * 512 + ((kcA ^ (rowA & 7)) << 4));
            const int kcB = ks * 2 + halfB;
            const uint32_t offB = (uint32_t)(rowB * 512 + ((kcB ^ (rowB & 7)) << 4));
            uint32_t al[4], bhp[2], blp[2];
            ldsm4(al, wl_addr + offA);
            ldsm2(bhp, hh_addr + offB);
            ldsm2(blp, hl_addr + offB);
            if (ks & 1) {
                mma16816(chh1, whreg[ks], bhp[0], bhp[1]);
                mma16816(chl1, whreg[ks], blp[0], blp[1]);
                mma16816(clh1, al, bhp[0], bhp[1]);
            } else {
                mma16816(chh0, whreg[ks], bhp[0], bhp[1]);
                mma16816(chl0, whreg[ks], blp[0], blp[1]);
                mma16816(clh0, al, bhp[0], bhp[1]);
            }
        }

        CP_WAIT(0);        // group B complete
        __syncthreads();

        // prefetch xp for next step (cp engine works under mma half 2)
        if (st + 1 < SEQ) {
            const int tn = dir ? (SEQ - 2 - st) : (st + 1);
            const int r = tid >> 2, c = tid & 3;
            const int pb = r >> 2, pq = r & 3;
            cp_async16(xsm_addr + (uint32_t)(((cur ^ 1) * 1088 + pb * 68 + pq * 16 + c * 4) * 4),
                       &g_xp[((size_t)tn * 64 + bbase + pb) * 2048 + dir * 1024 + pq * 256 + s16 + c * 4]);
            CP_COMMIT();
        }

        // mma second half: ks 8..15
#pragma unroll
        for (int ks = 8; ks < 16; ks++) {
            const int kcA = ks * 2 + halfA;
            const uint32_t offA = (uint32_t)(rowA * 512 + ((kcA ^ (rowA & 7)) << 4));
            const int kcB = ks * 2 + halfB;
            const uint32_t offB = (uint32_t)(rowB * 512 + ((kcB ^ (rowB & 7)) << 4));
            uint32_t al[4], bhp[2], blp[2];
            ldsm4(al, wl_addr + offA);
            ldsm2(bhp, hh_addr + offB);
            ldsm2(blp, hl_addr + offB);
            if (ks & 1) {
                mma16816(chh1, whreg[ks], bhp[0], bhp[1]);
                mma16816(chl1, whreg[ks], blp[0], blp[1]);
                mma16816(clh1, al, bhp[0], bhp[1]);
            } else {
                mma16816(chh0, whreg[ks], bhp[0], bhp[1]);
                mma16816(chl0, whreg[ks], blp[0], blp[1]);
                mma16816(clh0, al, bhp[0], bhp[1]);
            }
        }

        {
            const int r0  = mf * 16 + (lane >> 2);
            const int col = nb8 * 8 + 2 * (lane & 3);
            float2 v0 = make_float2(chh0[0] + chh1[0] + chl0[0] + chl1[0] + clh0[0] + clh1[0],
                                    chh0[1] + chh1[1] + chl0[1] + chl1[1] + clh0[1] + clh1[1]);
            float2 v1 = make_float2(chh0[2] + chh1[2] + chl0[2] + chl1[2] + clh0[2] + clh1[2],
                                    chh0[3] + chh1[3] + chl0[3] + chl1[3] + clh0[3] + clh1[3]);
            *(float2*)&gsm[r0 * 18 + col]       = v0;
            *(float2*)&gsm[(r0 + 8) * 18 + col] = v1;
        }
        __syncthreads();

        {
            const float* xq = xsm + cur * 1088 + b * 68;
            float a0 = gsm[(0 * 16 + j) * 18 + b] + xq[0 * 16 + j];
            float a1 = gsm[(1 * 16 + j) * 18 + b] + xq[1 * 16 + j];
            float a2 = gsm[(2 * 16 + j) * 18 + b] + xq[2 * 16 + j];
            float a3 = gsm[(3 * 16 + j) * 18 + b] + xq[3 * 16 + j];
            float i_ = __fdividef(1.f, 1.f + __expf(-a0));
            float f_ = __fdividef(1.f, 1.f + __expf(-a1));
            float g_ = tanhf(a2);
            float o_ = __fdividef(1.f, 1.f + __expf(-a3));
            float c_new = f_ * c_st + i_ * g_;
            float h_new = o_ * tanhf(c_new);
            bool  m = (tstep < len_b);
            c_st = m ? c_new : c_st;
            h_st = m ? h_new : h_st;
            __nv_bfloat16 hh = __float2bfloat16(h_st);
            __nv_bfloat16 hl = __float2bfloat16(h_st - __bfloat162float(hh));
            size_t o = ((size_t)(dir * 2 + (gbuf ^ 1)) * 64 + bbase + b) * 256 + s16 + j;
            g_hhi[o] = hh;
            g_hlo[o] = hl;
        }
        barrier_arrive(gcnt);
        g_hout[((size_t)(dir * SEQ + tstep) * HID + (s16 + j)) * 64 + bbase + b] = h_st;
        barrier_wait(gcnt, 16u * (st + 2));
    }
}

// ---------------- Kernel 3: logits = [h_f;h_b] @ W_clf^T + b_clf ----------------
__global__ __launch_bounds__(256) void clf_kernel(
    const float* __restrict__ Wclf, const float* __restrict__ bclf,
    float* __restrict__ out)
{
    __shared__ float Ws[32 * 65];
    __shared__ __align__(16) float hs[64 * 64];
    const int t   = blockIdx.x;
    const int tid = threadIdx.x;
    const int n   = tid & 31;
    const int bg  = tid >> 5;

    float acc[8];
#pragma unroll
    for (int i = 0; i < 8; i++) acc[i] = 0.f;

    for (int ch = 0; ch < 8; ch++) {
        const int dir = ch >> 2;
        const int jbase = (ch & 3) * 64;
        for (int l = tid; l < 2048; l += 256) {
            int nn = l >> 6, jj = l & 63;
            Ws[nn * 65 + jj] = Wclf[nn * 512 + dir * 256 + jbase + jj];
        }
        const float* hsrc = g_hout + ((size_t)(dir * SEQ + t) * HID + jbase) * 64;
#pragma unroll
        for (int r = 0; r < 4; r++)
            ((float4*)hs)[tid + r * 256] = __ldg(((const float4*)hsrc) + tid + r * 256);
        __syncthreads();
#pragma unroll 16
        for (int jj = 0; jj < 64; jj++) {
            float wv = Ws[n * 65 + jj];
            float4 hA = *(const float4*)&hs[jj * 64 + bg * 8];
            float4 hB = *(const float4*)&hs[jj * 64 + bg * 8 + 4];
            acc[0] += wv * hA.x; acc[1] += wv * hA.y; acc[2] += wv * hA.z; acc[3] += wv * hA.w;
            acc[4] += wv * hB.x; acc[5] += wv * hB.y; acc[6] += wv * hB.z; acc[7] += wv * hB.w;
        }
        __syncthreads();
    }
    const float bias = bclf[n];
#pragma unroll
    for (int bb = 0; bb < 8; bb++) {
        int b = bg * 8 + bb;
        out[((size_t)b * SEQ + t) * NK + n] = acc[bb] + bias;
    }
}

// ---------------- Kernel 4: Viterbi decode (smem-based) ----------------
__global__ __launch_bounds__(32) void viterbi_kernel(
    const float* __restrict__ logits, const int* __restrict__ lengths,
    const float* __restrict__ startt, const float* __restrict__ endt,
    const float* __restrict__ trans, float* __restrict__ preds, int write_preds)
{
    __shared__ float transT[32 * 33];
    __shared__ float sscore[2][32];
    __shared__ unsigned char hist[511][32];
    const int b = blockIdx.x;
    const int j = threadIdx.x;
    const int len = lengths[b];

#pragma unroll 4
    for (int i = 0; i < 32; i++) transT[j * 33 + i] = trans[i * 32 + j];

    const float* lg = logits + (size_t)b * SEQ * NK;
    float score = startt[j] + lg[j];
    float e_next = lg[NK + j];

    for (int t = 1; t < SEQ; t++) {
        const int buf = t & 1;
        sscore[buf][j] = score;
        __syncwarp();
        float e = e_next;
        if (t + 1 < SEQ) e_next = lg[(t + 1) * NK + j];

        float m0, m1; int a0, a1;
        float bestv = -3.4e38f; int besta = 0;
#pragma unroll
        for (int p = 0; p < 8; p++) {
            float4 s4 = *(const float4*)&sscore[buf][p * 4];
            float v0 = s4.x + transT[j * 33 + p * 4 + 0];
            float v1 = s4.y + transT[j * 33 + p * 4 + 1];
            float v2 = s4.z + transT[j * 33 + p * 4 + 2];
            float v3 = s4.w + transT[j * 33 + p * 4 + 3];
            bool t01 = v1 > v0; m0 = t01 ? v1 : v0; a0 = t01 ? p * 4 + 1 : p * 4;
            bool t23 = v3 > v2; m1 = t23 ? v3 : v2; a1 = t23 ? p * 4 + 3 : p * 4 + 2;
            bool tq = m1 > m0; float mq = tq ? m1 : m0; int aq = tq ? a1 : a0;
            bool tb = mq > bestv;
            bestv = tb ? mq : bestv;
            besta = tb ? aq : besta;
        }
        float nscore = bestv + e;
        bool msk = (t < len);
        hist[t - 1][j] = (unsigned char)(msk ? besta : j);
        score = msk ? nscore : score;
        __syncwarp();
    }
    score += endt[j];

    float bvv = score; int bii = j;
#pragma unroll
    for (int off = 16; off; off >>= 1) {
        float ov = __shfl_xor_sync(0xffffffffu, bvv, off);
        int   oi = __shfl_xor_sync(0xffffffffu, bii, off);
        if (ov > bvv || (ov == bvv && oi < bii)) { bvv = ov; bii = oi; }
    }
    __syncwarp();

    if (write_preds && j == 0) {
        int tag = bii;
        float* pp = preds + (size_t)b * SEQ;
        for (int t = SEQ - 2; t >= 0; t--) {
            pp[t + 1] = (float)(((t + 1) < len) ? tag : 0);
            tag = hist[t][tag];
        }
        pp[0] = (float)((0 < len) ? tag : 0);
    }
}

// ---------------- launch ----------------
extern "C" void kernel_launch(void* const* d_in, const int* in_sizes, int n_in,
                              void* d_out, int out_size)
{
    const float* x     = (const float*)d_in[0];
    const int*   lens  = (const int*)d_in[1];
    const float* Wih_f = (const float*)d_in[3];
    const float* Whh_f = (const float*)d_in[4];
    const float* b_f   = (const float*)d_in[5];
    const float* Wih_b = (const float*)d_in[6];
    const float* Whh_b = (const float*)d_in[7];
    const float* b_b   = (const float*)d_in[8];
    const float* W_clf = (const float*)d_in[9];
    const float* b_clf = (const float*)d_in[10];
    const float* st_t  = (const float*)d_in[11];
    const float* en_t  = (const float*)d_in[12];
    const float* trans = (const float*)d_in[13];
    float* out = (float*)d_out;

    __nv_bfloat16 *xhi, *xlo, *whi, *wlo;
    cudaGetSymbolAddress((void**)&xhi, g_xhi);
    cudaGetSymbolAddress((void**)&xlo, g_xlo);
    cudaGetSymbolAddress((void**)&whi, g_whi);
    cudaGetSymbolAddress((void**)&wlo, g_wlo);

    const int lstm_smem = 95232;
    cudaFuncSetAttribute(lstm_kernel, cudaFuncAttributeMaxDynamicSharedMemorySize, lstm_smem);
    const int gemm_smem = 3 * 16384;
    cudaFuncSetAttribute(gemm_xp_mma_kernel, cudaFuncAttributeMaxDynamicSharedMemorySize, gemm_smem);

    split_kernel<<<2048, 256>>>((const float4*)x, (uint2*)xhi, (uint2*)xlo, 32768 * 512 / 4, 1);
    split_kernel<<<128, 256>>>((const float4*)Wih_f, (uint2*)whi, (uint2*)wlo, 1024 * 512 / 4, 0);
    split_kernel<<<128, 256>>>((const float4*)Wih_b,
                               (uint2*)(whi + (size_t)1024 * 512),
                               (uint2*)(wlo + (size_t)1024 * 512), 1024 * 512 / 4, 0);

    gemm_xp_mma_kernel<<<dim3(16, 256), 256, gemm_smem>>>(b_f, b_b);

    lstm_kernel<<<128, 256, lstm_smem>>>(Whh_f, Whh_b, lens);
    clf_kernel<<<512, 256>>>(W_clf, b_clf, out);

    const int logits_elems = BATCH * SEQ * NK;      // 1048576
    const int preds_elems  = BATCH * SEQ;           // 32768
    int wp = (out_size >= logits_elems + preds_elems) ? 1 : 0;
    viterbi_kernel<<<64, 32>>>(out, lens, st_t, en_t, trans, out + logits_elems, wp);
}